// round 3
// baseline (speedup 1.0000x reference)
#include <cuda_runtime.h>
#include <cstdint>

#define BSZ 512
#define TSZ 512
#define FF  64
#define UU  512
#define PP  32
#define K1  (UU + FF + PP)   // 608
#define NCTA 128
#define NTHR 256
#define KC  16

// ---- device-global scratch (no allocations allowed) ----
__device__ float g_W0[K1 * UU];        // rows 0-511 WA0, 512-607 WB0
__device__ float g_W1[2 * UU * UU];    // rows 0-511 WA1, 512-1023 E1=WC0@WBr0
__device__ float g_W2[2 * UU * UU];    // rows 0-511 WA2, 512-1023 E2=WC1@WBr1
__device__ float g_Wo[UU * PP];        // Eo = WC2@Wout
__device__ float g_c0[UU], g_c1[UU], g_c2[UU], g_co[PP];
__device__ float g_HS[2][3][BSZ * UU]; // ping-pong hidden states
__device__ float g_ACC[BSZ * PP];
__device__ unsigned g_bar;

__device__ __forceinline__ void fma2(unsigned long long& d, unsigned long long a,
                                     unsigned long long b) {
    asm("fma.rn.f32x2 %0, %1, %2, %0;" : "+l"(d) : "l"(a), "l"(b));
}
__device__ __forceinline__ void unpack2(unsigned long long v, float& lo, float& hi) {
    asm("mov.b64 {%0, %1}, %2;" : "=f"(lo), "=f"(hi) : "l"(v));
}

// ---- grid barrier: 128 CTAs, all co-resident in wave 1 ----
__device__ __forceinline__ void gsync(unsigned& barn) {
    barn += 1;
    const unsigned target = barn * NCTA;
    __syncthreads();
    if (threadIdx.x == 0) {
        __threadfence();
        atomicAdd(&g_bar, 1u);
        unsigned v;
        do {
            asm volatile("ld.acquire.gpu.u32 %0, [%1];" : "=r"(v) : "l"(&g_bar) : "memory");
            if (v >= target) break;
            __nanosleep(32);
        } while (true);
    }
    __syncthreads();
}

// ---- A-operand fetch across concatenated K segments ----
__device__ __forceinline__ float4 fetchA(int phase, const float* a0, const float* a1,
                                         const float* x, int t, int b, int k) {
    if (k < UU)
        return __ldcg((const float4*)(a0 + (size_t)b * UU + k));
    if (phase == 1) {
        if (k < UU + FF)
            return __ldg((const float4*)(x + ((size_t)b * TSZ + t) * FF + (k - UU)));
        return __ldcg((const float4*)(g_ACC + b * PP + (k - UU - FF)));
    }
    return __ldcg((const float4*)(a1 + (size_t)b * UU + (k - UU)));
}

// ---- main GEMM phase: C[512,512] tiled 64x32 per CTA, FFMA2 inner loop ----
__device__ void gemm_tile(int phase, const float* a0, const float* a1,
                          const float* __restrict__ x, int t,
                          const float* __restrict__ W, int Ktot,
                          const float* __restrict__ cb, float* __restrict__ dst) {
    __shared__ __align__(16) float As2[2][KC][134];  // duplicated pairs, padded
    __shared__ __align__(16) float Bs[2][KC][32];

    const int tid = threadIdx.x;
    const int b0 = (blockIdx.x >> 4) * 64;
    const int n0 = (blockIdx.x & 15) * 32;
    const int tr = tid >> 3;          // rows 2tr, 2tr+1
    const int tc = tid & 7;           // cols 4tc..4tc+3
    const int sb = tid >> 2;          // A-stage row 0..63
    const int sq = tid & 3;           // A-stage k-quad
    const int bkk = tid >> 3;         // B-stage kk (tid<128)
    const int bc = tid & 7;

    unsigned long long acc00 = 0, acc01 = 0, acc10 = 0, acc11 = 0;
    const int ntiles = Ktot / KC;

    float4 ra = fetchA(phase, a0, a1, x, t, b0 + sb, 4 * sq);
    float4 rb;
    if (tid < 128) rb = __ldg((const float4*)(W + (size_t)bkk * UU + n0 + 4 * bc));
    {
        *(float2*)&As2[0][4 * sq + 0][2 * sb] = make_float2(ra.x, ra.x);
        *(float2*)&As2[0][4 * sq + 1][2 * sb] = make_float2(ra.y, ra.y);
        *(float2*)&As2[0][4 * sq + 2][2 * sb] = make_float2(ra.z, ra.z);
        *(float2*)&As2[0][4 * sq + 3][2 * sb] = make_float2(ra.w, ra.w);
        if (tid < 128) *(float4*)&Bs[0][bkk][4 * bc] = rb;
    }
    __syncthreads();

    int buf = 0;
    for (int kt = 0; kt < ntiles; kt++) {
        const int k0n = (kt + 1) * KC;
        const bool more = (kt + 1 < ntiles);
        if (more) {
            ra = fetchA(phase, a0, a1, x, t, b0 + sb, k0n + 4 * sq);
            if (tid < 128)
                rb = __ldg((const float4*)(W + (size_t)(k0n + bkk) * UU + n0 + 4 * bc));
        }
#pragma unroll
        for (int kk = 0; kk < KC; kk++) {
            const unsigned long long a0d = *(const unsigned long long*)&As2[buf][kk][4 * tr];
            const unsigned long long a1d = *(const unsigned long long*)&As2[buf][kk][4 * tr + 2];
            const ulonglong2 bv = *(const ulonglong2*)&Bs[buf][kk][4 * tc];
            fma2(acc00, a0d, bv.x);
            fma2(acc01, a0d, bv.y);
            fma2(acc10, a1d, bv.x);
            fma2(acc11, a1d, bv.y);
        }
        if (more) {
            const int nb = buf ^ 1;
            *(float2*)&As2[nb][4 * sq + 0][2 * sb] = make_float2(ra.x, ra.x);
            *(float2*)&As2[nb][4 * sq + 1][2 * sb] = make_float2(ra.y, ra.y);
            *(float2*)&As2[nb][4 * sq + 2][2 * sb] = make_float2(ra.z, ra.z);
            *(float2*)&As2[nb][4 * sq + 3][2 * sb] = make_float2(ra.w, ra.w);
            if (tid < 128) *(float4*)&Bs[nb][bkk][4 * bc] = rb;
        }
        __syncthreads();
        buf ^= 1;
    }

    const float4 cbv = __ldg((const float4*)(cb + n0 + 4 * tc));
    float o0, o1, o2, o3;
    const int r0 = b0 + 2 * tr;
    unpack2(acc00, o0, o1);
    unpack2(acc01, o2, o3);
    *(float4*)(dst + (size_t)r0 * UU + n0 + 4 * tc) =
        make_float4(o0 + cbv.x, o1 + cbv.y, o2 + cbv.z, o3 + cbv.w);
    unpack2(acc10, o0, o1);
    unpack2(acc11, o2, o3);
    *(float4*)(dst + (size_t)(r0 + 1) * UU + n0 + 4 * tc) =
        make_float4(o0 + cbv.x, o1 + cbv.y, o2 + cbv.z, o3 + cbv.w);
}

// ---- phase 4: res = ns2 @ Eo + co; acc += res; out[b,t,:] = res ----
__device__ void phase4(int t, const float* __restrict__ h2, float* __restrict__ out) {
    __shared__ __align__(16) float Hs[4 * UU];
    const int tid = threadIdx.x;
    const int b0 = blockIdx.x * 4;
    const float4* src = (const float4*)(h2 + (size_t)b0 * UU);
    for (int i = tid; i < 4 * UU / 4; i += NTHR)
        ((float4*)Hs)[i] = __ldcg(src + i);
    __syncthreads();
    if (tid < 128) {
        const int r = tid >> 5, c = tid & 31;
        const int b = b0 + r;
        const float* hr = Hs + r * UU;
        float s0 = 0.f, s1 = 0.f, s2 = 0.f, s3 = 0.f;
#pragma unroll 4
        for (int k = 0; k < UU; k += 4) {
            s0 = fmaf(hr[k + 0], __ldg(&g_Wo[(k + 0) * PP + c]), s0);
            s1 = fmaf(hr[k + 1], __ldg(&g_Wo[(k + 1) * PP + c]), s1);
            s2 = fmaf(hr[k + 2], __ldg(&g_Wo[(k + 2) * PP + c]), s2);
            s3 = fmaf(hr[k + 3], __ldg(&g_Wo[(k + 3) * PP + c]), s3);
        }
        const float s = (s0 + s1) + (s2 + s3) + __ldg(&g_co[c]);
        const int ai = b * PP + c;
        g_ACC[ai] = __ldcg(&g_ACC[ai]) + s;
        out[((size_t)b * TSZ + t) * PP + c] = s;
    }
    __syncthreads();
}

// ---- persistent time loop ----
__global__ void __launch_bounds__(NTHR, 1)
rnn_run(const float* __restrict__ x, float* __restrict__ out) {
    unsigned barn = 0;
    for (int t = 0; t < TSZ; t++) {
        const int cur = t & 1, nxt = cur ^ 1;
        gemm_tile(1, g_HS[cur][0], nullptr,      x, t, g_W0, K1,     g_c0, g_HS[nxt][0]);
        gsync(barn);
        gemm_tile(2, g_HS[cur][1], g_HS[nxt][0], x, t, g_W1, 2 * UU, g_c1, g_HS[nxt][1]);
        gsync(barn);
        gemm_tile(3, g_HS[cur][2], g_HS[nxt][1], x, t, g_W2, 2 * UU, g_c2, g_HS[nxt][2]);
        gsync(barn);
        phase4(t, g_HS[nxt][2], out);
        gsync(barn);
    }
}

// ---- one-time setup kernels ----
__global__ void init_state() {
    const size_t tid = (size_t)blockIdx.x * blockDim.x + threadIdx.x;
    const size_t stride = (size_t)gridDim.x * blockDim.x;
    float* hs = &g_HS[0][0][0];
    for (size_t i = tid; i < (size_t)2 * 3 * BSZ * UU; i += stride) hs[i] = 0.f;
    for (size_t i = tid; i < (size_t)BSZ * PP; i += stride) g_ACC[i] = 0.f;
    if (tid == 0) g_bar = 0u;
}

__global__ void pack_weights(const float* __restrict__ WA, const float* __restrict__ WB0) {
    const size_t tid = (size_t)blockIdx.x * blockDim.x + threadIdx.x;
    const size_t stride = (size_t)gridDim.x * blockDim.x;
    for (size_t i = tid; i < (size_t)K1 * UU; i += stride) {
        const int k = (int)(i >> 9), n = (int)(i & 511);
        g_W0[i] = (k < UU) ? WA[(size_t)k * UU + n] : WB0[(size_t)(k - UU) * UU + n];
    }
    for (size_t i = tid; i < (size_t)UU * UU; i += stride) {
        g_W1[i] = WA[(size_t)UU * UU + i];
        g_W2[i] = WA[(size_t)2 * UU * UU + i];
    }
}

// which: 0 -> E1 into g_W1[512:], 1 -> E2 into g_W2[512:], 2 -> Eo into g_Wo
__global__ void gemm_pre(const float* __restrict__ A, const float* __restrict__ Bm, int which) {
    float* C = (which == 0) ? g_W1 + UU * UU : (which == 1) ? g_W2 + UU * UU : g_Wo;
    const int N = (which == 2) ? PP : UU;
    __shared__ float As_[32][33], Bs_[32][33];
    const int tx = threadIdx.x, ty = threadIdx.y;
    const int row = blockIdx.y * 32 + ty;
    const int col = blockIdx.x * 32 + tx;
    float s = 0.f;
    for (int k0 = 0; k0 < UU; k0 += 32) {
        As_[ty][tx] = A[(size_t)row * UU + k0 + tx];
        Bs_[ty][tx] = (col < N) ? Bm[(size_t)(k0 + ty) * N + col] : 0.f;
        __syncthreads();
#pragma unroll
        for (int kk = 0; kk < 32; kk++) s = fmaf(As_[ty][kk], Bs_[kk][tx], s);
        __syncthreads();
    }
    if (col < N) C[(size_t)row * N + col] = s;
}

__global__ void make_biases(const float* __restrict__ bA, const float* __restrict__ bB0,
                            const float* __restrict__ bBr, const float* __restrict__ bC,
                            const float* __restrict__ WBr, const float* __restrict__ Wout,
                            const float* __restrict__ bout) {
    const int j = threadIdx.x;
    if (j < UU) {
        g_c0[j] = bA[j] + bB0[j];
        float s1 = 0.f, s2 = 0.f;
        for (int k = 0; k < UU; k++) {
            s1 = fmaf(bC[k], WBr[(size_t)k * UU + j], s1);
            s2 = fmaf(bC[UU + k], WBr[(size_t)UU * UU + (size_t)k * UU + j], s2);
        }
        g_c1[j] = bA[UU + j] + bBr[j] + s1;
        g_c2[j] = bA[2 * UU + j] + bBr[UU + j] + s2;
    }
    if (j < PP) {
        float s = 0.f;
        for (int k = 0; k < UU; k++) s = fmaf(bC[2 * UU + k], Wout[(size_t)k * PP + j], s);
        g_co[j] = bout[j] + s;
    }
}

// ---- entry ----
extern "C" void kernel_launch(void* const* d_in, const int* in_sizes, int n_in,
                              void* d_out, int out_size) {
    const float* x    = (const float*)d_in[0];
    const float* WA   = (const float*)d_in[1];
    const float* bA   = (const float*)d_in[2];
    const float* WB0  = (const float*)d_in[3];
    const float* bB0  = (const float*)d_in[4];
    const float* WBr  = (const float*)d_in[5];
    const float* bBr  = (const float*)d_in[6];
    const float* WC   = (const float*)d_in[7];
    const float* bC   = (const float*)d_in[8];
    const float* Wout = (const float*)d_in[9];
    const float* bout = (const float*)d_in[10];
    float* out = (float*)d_out;

    pack_weights<<<256, 256>>>(WA, WB0);

    dim3 blk(32, 32);
    gemm_pre<<<dim3(16, 16), blk>>>(WC,               WBr,               0);
    gemm_pre<<<dim3(16, 16), blk>>>(WC + UU * UU,     WBr + UU * UU,     1);
    gemm_pre<<<dim3(1, 16),  blk>>>(WC + 2 * UU * UU, Wout,              2);

    make_biases<<<1, 512>>>(bA, bB0, bBr, bC, WBr, Wout, bout);
    init_state<<<256, 256>>>();

    rnn_run<<<NCTA, NTHR>>>(x, out);
}